// round 9
// baseline (speedup 1.0000x reference)
#include <cuda_runtime.h>
#include <cstdint>

// Gauss-Legendre tables for n = 1..5 (numpy-double -> float32 cast).
__constant__ float XI_TAB[5][5] = {
    { 0.0f, 0.f, 0.f, 0.f, 0.f },
    { -0.5773502691896258f, 0.5773502691896258f, 0.f, 0.f, 0.f },
    { -0.7745966692414834f, 0.0f, 0.7745966692414834f, 0.f, 0.f },
    { -0.8611363115940526f, -0.3399810435848563f, 0.3399810435848563f, 0.8611363115940526f, 0.f },
    { 0.0f, -0.5384693101056831f, 0.5384693101056831f, -0.9061798459386640f, 0.9061798459386640f },
};
__constant__ float W_TAB[5][5] = {
    { 2.0f, 0.f, 0.f, 0.f, 0.f },
    { 1.0f, 1.0f, 0.f, 0.f, 0.f },
    { 0.5555555555555556f, 0.8888888888888889f, 0.5555555555555556f, 0.f, 0.f },
    { 0.3478548451374538f, 0.6521451548625461f, 0.6521451548625461f, 0.3478548451374538f, 0.f },
    { 0.5688888888888889f, 0.4786286704993665f, 0.4786286704993665f, 0.2369268850561891f, 0.2369268850561891f },
};

// Exact reference rounding sequence per Gauss point (no FMA contraction —
// the x_g - x1 cancellation at x1 ~ 4e6 must quantize identically).
template <int G>
__device__ __forceinline__ void eval_elem(float x1, float x2, float v1, float v2,
                                          float* f_int, float* f_xg, float* f_djw)
{
    float dx   = __fsub_rn(x2, x1);
    float detJ = __fmul_rn(dx, 0.5f);
#pragma unroll
    for (int g = 0; g < G; ++g) {
        float xi  = XI_TAB[G - 1][g];
        float w   = W_TAB[G - 1][g];
        float t   = __fmul_rn(__fmul_rn(__fadd_rn(xi, 1.0f), dx), 0.5f);
        float x_g = __fadd_rn(x1, t);
        float num = __fmul_rn(2.0f, __fsub_rn(x_g, x1));
        float ref = __fsub_rn(__fdiv_rn(num, dx), 1.0f);
        float N0  = __fadd_rn(__fmul_rn(-0.5f, ref), 0.5f);
        float N1  = __fadd_rn(__fmul_rn(0.5f, ref), 0.5f);
        f_int[g] = __fadd_rn(__fmul_rn(N0, v1), __fmul_rn(N1, v2));
        f_xg[g]  = x_g;
        f_djw[g] = __fmul_rn(detJ, w);
    }
}

// 4 elements per thread: vectorized conn loads (2x LDG.128), vectorized smem
// staging (STS.128, per-thread 48B-aligned runs, conflict-free: 12t mod 32
// distinct within each store phase), coalesced STG.128 flush.
template <int G, int BLOCK, int EPT>
__global__ void __launch_bounds__(BLOCK) meshnn1d_kernel(
    const float* __restrict__ coords,
    const float* __restrict__ vals,
    const int*   __restrict__ conn,    // [E,2] int32, 1-based
    float* __restrict__ out,           // [3, E, G] : interpol | x_g | detJ_w
    int E)
{
    constexpr int ELEM_BLOCK = BLOCK * EPT;
    constexpr int FPT        = EPT * G;          // floats per thread per section
    __shared__ float s_buf[3][ELEM_BLOCK * G];

    const int tid        = threadIdx.x;
    const int blockStart = blockIdx.x * ELEM_BLOCK;
    const int nElem      = min(ELEM_BLOCK, E - blockStart);  // elements this block
    const int e0         = tid * EPT;                        // local element base

    if (e0 + EPT <= nElem) {
        // --- full fast path: 4 elements ---
        const int4* c4 = reinterpret_cast<const int4*>(conn) +
                         ((size_t)(blockStart + e0) >> 1);
        int4 ca = c4[0];   // elements e0, e0+1
        int4 cb = c4[1];   // elements e0+2, e0+3

        int i1[EPT] = { ca.x - 1, ca.z - 1, cb.x - 1, cb.z - 1 };
        int i2[EPT] = { ca.y - 1, ca.w - 1, cb.y - 1, cb.w - 1 };

        float x1[EPT], x2[EPT], v1[EPT], v2[EPT];
#pragma unroll
        for (int k = 0; k < EPT; ++k) { x1[k] = coords[i1[k]]; x2[k] = coords[i2[k]]; }
#pragma unroll
        for (int k = 0; k < EPT; ++k) { v1[k] = vals[i1[k]];   v2[k] = vals[i2[k]]; }

        float f_int[FPT], f_xg[FPT], f_djw[FPT];
#pragma unroll
        for (int k = 0; k < EPT; ++k)
            eval_elem<G>(x1[k], x2[k], v1[k], v2[k],
                         f_int + k * G, f_xg + k * G, f_djw + k * G);

        // vectorized staging: FPT is a multiple of 4 for EPT=4, any G
        static_assert(FPT % 4 == 0, "FPT must be divisible by 4");
        float4* d0 = reinterpret_cast<float4*>(&s_buf[0][e0 * G]);
        float4* d1 = reinterpret_cast<float4*>(&s_buf[1][e0 * G]);
        float4* d2 = reinterpret_cast<float4*>(&s_buf[2][e0 * G]);
#pragma unroll
        for (int j = 0; j < FPT / 4; ++j) {
            d0[j] = make_float4(f_int[4*j], f_int[4*j+1], f_int[4*j+2], f_int[4*j+3]);
            d1[j] = make_float4(f_xg[4*j],  f_xg[4*j+1],  f_xg[4*j+2],  f_xg[4*j+3]);
            d2[j] = make_float4(f_djw[4*j], f_djw[4*j+1], f_djw[4*j+2], f_djw[4*j+3]);
        }
    } else if (e0 < nElem) {
        // --- tail: scalar per element ---
        for (int k = 0; k < EPT && e0 + k < nElem; ++k) {
            int e = blockStart + e0 + k;
            int2 c = reinterpret_cast<const int2*>(conn)[e];
            int i1 = c.x - 1, i2 = c.y - 1;
            float f_int[G], f_xg[G], f_djw[G];
            eval_elem<G>(coords[i1], coords[i2], vals[i1], vals[i2], f_int, f_xg, f_djw);
#pragma unroll
            for (int g = 0; g < G; ++g) {
                s_buf[0][(e0 + k) * G + g] = f_int[g];
                s_buf[1][(e0 + k) * G + g] = f_xg[g];
                s_buf[2][(e0 + k) * G + g] = f_djw[g];
            }
        }
    }
    __syncthreads();

    const size_t EG   = (size_t)E * G;
    const size_t base = (size_t)blockStart * G;
    const int nFloats = nElem * G;

    if (nElem == ELEM_BLOCK) {
        constexpr int NV = ELEM_BLOCK * G / 4;
#pragma unroll
        for (int sec = 0; sec < 3; ++sec) {
            const float4* src = reinterpret_cast<const float4*>(&s_buf[sec][0]);
            size_t off = (size_t)sec * EG + base;
            if ((off & 3) == 0) {
                float4* dst = reinterpret_cast<float4*>(out + off);
#pragma unroll 2
                for (int i = tid; i < NV; i += BLOCK) dst[i] = src[i];
            } else {
                for (int i = tid; i < ELEM_BLOCK * G; i += BLOCK)
                    out[off + i] = s_buf[sec][i];
            }
        }
    } else {
#pragma unroll
        for (int sec = 0; sec < 3; ++sec) {
            size_t off = (size_t)sec * EG + base;
            for (int i = tid; i < nFloats; i += BLOCK)
                out[off + i] = s_buf[sec][i];
        }
    }
}

template <int G>
static void launch(const float* coords, const float* vals, const int* conn,
                   float* out, int E)
{
    constexpr int BLOCK = 256;
    constexpr int EPT   = 4;
    int blocks = (E + BLOCK * EPT - 1) / (BLOCK * EPT);
    meshnn1d_kernel<G, BLOCK, EPT><<<blocks, BLOCK>>>(coords, vals, conn, out, E);
}

extern "C" void kernel_launch(void* const* d_in, const int* in_sizes, int n_in,
                              void* d_out, int out_size)
{
    const float* coords = (const float*)d_in[0];
    const float* vals   = (const float*)d_in[1];
    const int*   conn   = (const int*)d_in[2];
    float*       out    = (float*)d_out;

    int E = in_sizes[2] / 2;
    int G = (E > 0) ? (int)((long long)out_size / (3LL * E)) : 3;
    if (G < 1) G = 1;
    if (G > 5) G = 5;

    switch (G) {
        case 1: launch<1>(coords, vals, conn, out, E); break;
        case 2: launch<2>(coords, vals, conn, out, E); break;
        case 3: launch<3>(coords, vals, conn, out, E); break;
        case 4: launch<4>(coords, vals, conn, out, E); break;
        case 5: launch<5>(coords, vals, conn, out, E); break;
    }
}

// round 10
// speedup vs baseline: 1.2168x; 1.2168x over previous
#include <cuda_runtime.h>
#include <cstdint>

// Gauss-Legendre tables for n = 1..5 (numpy-double -> float32 cast).
__constant__ float XI_TAB[5][5] = {
    { 0.0f, 0.f, 0.f, 0.f, 0.f },
    { -0.5773502691896258f, 0.5773502691896258f, 0.f, 0.f, 0.f },
    { -0.7745966692414834f, 0.0f, 0.7745966692414834f, 0.f, 0.f },
    { -0.8611363115940526f, -0.3399810435848563f, 0.3399810435848563f, 0.8611363115940526f, 0.f },
    { 0.0f, -0.5384693101056831f, 0.5384693101056831f, -0.9061798459386640f, 0.9061798459386640f },
};
__constant__ float W_TAB[5][5] = {
    { 2.0f, 0.f, 0.f, 0.f, 0.f },
    { 1.0f, 1.0f, 0.f, 0.f, 0.f },
    { 0.5555555555555556f, 0.8888888888888889f, 0.5555555555555556f, 0.f, 0.f },
    { 0.3478548451374538f, 0.6521451548625461f, 0.6521451548625461f, 0.3478548451374538f, 0.f },
    { 0.5688888888888889f, 0.4786286704993665f, 0.4786286704993665f, 0.2369268850561891f, 0.2369268850561891f },
};

// Exact reference rounding sequence per Gauss point (no FMA contraction —
// the x_g - x1 cancellation at x1 ~ 4e6 must quantize identically).
template <int G>
__device__ __forceinline__ void eval_elem(float x1, float x2, float v1, float v2,
                                          float* f_int, float* f_xg, float* f_djw)
{
    float dx   = __fsub_rn(x2, x1);
    float detJ = __fmul_rn(dx, 0.5f);
#pragma unroll
    for (int g = 0; g < G; ++g) {
        float xi  = XI_TAB[G - 1][g];
        float w   = W_TAB[G - 1][g];
        float t   = __fmul_rn(__fmul_rn(__fadd_rn(xi, 1.0f), dx), 0.5f);
        float x_g = __fadd_rn(x1, t);
        float num = __fmul_rn(2.0f, __fsub_rn(x_g, x1));
        float ref = __fsub_rn(__fdiv_rn(num, dx), 1.0f);
        float N0  = __fadd_rn(__fmul_rn(-0.5f, ref), 0.5f);
        float N1  = __fadd_rn(__fmul_rn(0.5f, ref), 0.5f);
        f_int[g] = __fadd_rn(__fmul_rn(N0, v1), __fmul_rn(N1, v2));
        f_xg[g]  = x_g;
        f_djw[g] = __fmul_rn(detJ, w);
    }
}

// EPT=2: one LDG.128 conn load per thread, float2-vectorized smem staging
// (3x STS.64 per section, conflict-free: word addr 6t -> 3t mod 16 distinct),
// coalesced STG.128 flush with evict-first policy on the streamed output.
template <int G, int BLOCK, int EPT>
__global__ void __launch_bounds__(BLOCK) meshnn1d_kernel(
    const float* __restrict__ coords,
    const float* __restrict__ vals,
    const int*   __restrict__ conn,    // [E,2] int32, 1-based
    float* __restrict__ out,           // [3, E, G] : interpol | x_g | detJ_w
    int E)
{
    constexpr int ELEM_BLOCK = BLOCK * EPT;
    constexpr int FPT        = EPT * G;          // floats per thread per section
    __shared__ float s_buf[3][ELEM_BLOCK * G];

    const int tid        = threadIdx.x;
    const int blockStart = blockIdx.x * ELEM_BLOCK;
    const int nElem      = min(ELEM_BLOCK, E - blockStart);
    const int e0         = tid * EPT;            // local element base

    if (e0 + EPT <= nElem) {
        // --- fast path: 2 elements, one 16B conn load ---
        // (blockStart + e0) is even: blockStart % 512 == 0, e0 = 2*tid.
        int4 c = __ldcs(reinterpret_cast<const int4*>(conn) +
                        ((size_t)(blockStart + e0) >> 1));
        int i1a = c.x - 1, i2a = c.y - 1;
        int i1b = c.z - 1, i2b = c.w - 1;

        float x1a = coords[i1a], x2a = coords[i2a];
        float x1b = coords[i1b], x2b = coords[i2b];
        float v1a = vals[i1a],   v2a = vals[i2a];
        float v1b = vals[i1b],   v2b = vals[i2b];

        float f_int[FPT], f_xg[FPT], f_djw[FPT];
        eval_elem<G>(x1a, x2a, v1a, v2a, f_int,     f_xg,     f_djw);
        eval_elem<G>(x1b, x2b, v1b, v2b, f_int + G, f_xg + G, f_djw + G);

        // float2-vectorized staging (FPT = 2*G is even for all G)
        static_assert(FPT % 2 == 0, "FPT must be even");
        float2* d0 = reinterpret_cast<float2*>(&s_buf[0][e0 * G]);
        float2* d1 = reinterpret_cast<float2*>(&s_buf[1][e0 * G]);
        float2* d2 = reinterpret_cast<float2*>(&s_buf[2][e0 * G]);
#pragma unroll
        for (int j = 0; j < FPT / 2; ++j) {
            d0[j] = make_float2(f_int[2*j], f_int[2*j+1]);
            d1[j] = make_float2(f_xg[2*j],  f_xg[2*j+1]);
            d2[j] = make_float2(f_djw[2*j], f_djw[2*j+1]);
        }
    } else if (e0 < nElem) {
        // --- tail: scalar per element ---
        for (int k = 0; k < EPT && e0 + k < nElem; ++k) {
            int e = blockStart + e0 + k;
            int2 c = reinterpret_cast<const int2*>(conn)[e];
            int i1 = c.x - 1, i2 = c.y - 1;
            float f_int[G], f_xg[G], f_djw[G];
            eval_elem<G>(coords[i1], coords[i2], vals[i1], vals[i2], f_int, f_xg, f_djw);
#pragma unroll
            for (int g = 0; g < G; ++g) {
                s_buf[0][(e0 + k) * G + g] = f_int[g];
                s_buf[1][(e0 + k) * G + g] = f_xg[g];
                s_buf[2][(e0 + k) * G + g] = f_djw[g];
            }
        }
    }
    __syncthreads();

    const size_t EG   = (size_t)E * G;
    const size_t base = (size_t)blockStart * G;
    const int nFloats = nElem * G;

    if (nElem == ELEM_BLOCK) {
        constexpr int NV = ELEM_BLOCK * G / 4;   // float4s per section
#pragma unroll
        for (int sec = 0; sec < 3; ++sec) {
            const float4* src = reinterpret_cast<const float4*>(&s_buf[sec][0]);
            size_t off = (size_t)sec * EG + base;
            if ((off & 3) == 0) {
                float4* dst = reinterpret_cast<float4*>(out + off);
                for (int i = tid; i < NV; i += BLOCK) __stcs(dst + i, src[i]);
            } else {
                for (int i = tid; i < ELEM_BLOCK * G; i += BLOCK)
                    __stcs(out + off + i, s_buf[sec][i]);
            }
        }
    } else {
#pragma unroll
        for (int sec = 0; sec < 3; ++sec) {
            size_t off = (size_t)sec * EG + base;
            for (int i = tid; i < nFloats; i += BLOCK)
                __stcs(out + off + i, s_buf[sec][i]);
        }
    }
}

template <int G>
static void launch(const float* coords, const float* vals, const int* conn,
                   float* out, int E)
{
    constexpr int BLOCK = 256;
    constexpr int EPT   = 2;
    int blocks = (E + BLOCK * EPT - 1) / (BLOCK * EPT);
    meshnn1d_kernel<G, BLOCK, EPT><<<blocks, BLOCK>>>(coords, vals, conn, out, E);
}

extern "C" void kernel_launch(void* const* d_in, const int* in_sizes, int n_in,
                              void* d_out, int out_size)
{
    const float* coords = (const float*)d_in[0];
    const float* vals   = (const float*)d_in[1];
    const int*   conn   = (const int*)d_in[2];
    float*       out    = (float*)d_out;

    int E = in_sizes[2] / 2;
    int G = (E > 0) ? (int)((long long)out_size / (3LL * E)) : 3;
    if (G < 1) G = 1;
    if (G > 5) G = 5;

    switch (G) {
        case 1: launch<1>(coords, vals, conn, out, E); break;
        case 2: launch<2>(coords, vals, conn, out, E); break;
        case 3: launch<3>(coords, vals, conn, out, E); break;
        case 4: launch<4>(coords, vals, conn, out, E); break;
        case 5: launch<5>(coords, vals, conn, out, E); break;
    }
}

// round 11
// speedup vs baseline: 1.3045x; 1.0720x over previous
#include <cuda_runtime.h>
#include <cstdint>

// Gauss-Legendre tables for n = 1..5 (numpy-double -> float32 cast).
__constant__ float XI_TAB[5][5] = {
    { 0.0f, 0.f, 0.f, 0.f, 0.f },
    { -0.5773502691896258f, 0.5773502691896258f, 0.f, 0.f, 0.f },
    { -0.7745966692414834f, 0.0f, 0.7745966692414834f, 0.f, 0.f },
    { -0.8611363115940526f, -0.3399810435848563f, 0.3399810435848563f, 0.8611363115940526f, 0.f },
    { 0.0f, -0.5384693101056831f, 0.5384693101056831f, -0.9061798459386640f, 0.9061798459386640f },
};
__constant__ float W_TAB[5][5] = {
    { 2.0f, 0.f, 0.f, 0.f, 0.f },
    { 1.0f, 1.0f, 0.f, 0.f, 0.f },
    { 0.5555555555555556f, 0.8888888888888889f, 0.5555555555555556f, 0.f, 0.f },
    { 0.3478548451374538f, 0.6521451548625461f, 0.6521451548625461f, 0.3478548451374538f, 0.f },
    { 0.5688888888888889f, 0.4786286704993665f, 0.4786286704993665f, 0.2369268850561891f, 0.2369268850561891f },
};

// Rounding-critical path (must match reference bit-exactly): t and x_g.
// x_g = fl(x1 + t) quantizes t to ulp(x1) ~ 0.25; any deviation there shifts
// ref by O(0.1). Given bit-exact x_g: (x_g - x1) is exact (Sterbenz),
// 2*(...) is exact, so replacing the correctly-rounded division by
// num * rcp(dx) and FMA-folding the shape functions perturbs results by
// only ~1e-7 relative — far under the 1e-3 threshold. This deletes three
// ~10-instruction __fdiv_rn chains per element.
template <int G>
__device__ __forceinline__ void eval_elem(float x1, float x2, float v1, float v2,
                                          float* f_int, float* f_xg, float* f_djw)
{
    float dx   = __fsub_rn(x2, x1);
    float detJ = __fmul_rn(dx, 0.5f);
    float rcp  = __frcp_rn(dx);                       // one reciprocal per element
    float d    = __fmul_rn(0.5f, __fsub_rn(v2, v1));  // interpol = ref*d + s
    float s    = __fmul_rn(0.5f, __fadd_rn(v1, v2));
#pragma unroll
    for (int g = 0; g < G; ++g) {
        float xi  = XI_TAB[G - 1][g];
        float w   = W_TAB[G - 1][g];
        // exact reference sequence for t and x_g (no contraction)
        float t   = __fmul_rn(__fmul_rn(__fadd_rn(xi, 1.0f), dx), 0.5f);
        float x_g = __fadd_rn(x1, t);
        float num = __fmul_rn(2.0f, __fsub_rn(x_g, x1));   // exact
        float ref = __fmaf_rn(num, rcp, -1.0f);
        f_int[g] = __fmaf_rn(ref, d, s);
        f_xg[g]  = x_g;
        f_djw[g] = __fmul_rn(detJ, w);
    }
}

// EPT=2: one LDG.128 conn load per thread, float2 smem staging (conflict-free),
// coalesced STG.128 flush, evict-first on streamed output. min-8-blocks launch
// bound forces 32 regs -> ~full occupancy (smem 18.4KB x 8 fits 228KB).
template <int G, int BLOCK, int EPT>
__global__ void __launch_bounds__(BLOCK, 8) meshnn1d_kernel(
    const float* __restrict__ coords,
    const float* __restrict__ vals,
    const int*   __restrict__ conn,    // [E,2] int32, 1-based
    float* __restrict__ out,           // [3, E, G] : interpol | x_g | detJ_w
    int E)
{
    constexpr int ELEM_BLOCK = BLOCK * EPT;
    constexpr int FPT        = EPT * G;
    __shared__ float s_buf[3][ELEM_BLOCK * G];

    const int tid        = threadIdx.x;
    const int blockStart = blockIdx.x * ELEM_BLOCK;
    const int nElem      = min(ELEM_BLOCK, E - blockStart);
    const int e0         = tid * EPT;

    if (e0 + EPT <= nElem) {
        int4 c = __ldcs(reinterpret_cast<const int4*>(conn) +
                        ((size_t)(blockStart + e0) >> 1));
        int i1a = c.x - 1, i2a = c.y - 1;
        int i1b = c.z - 1, i2b = c.w - 1;

        float x1a = coords[i1a], x2a = coords[i2a];
        float x1b = coords[i1b], x2b = coords[i2b];
        float v1a = vals[i1a],   v2a = vals[i2a];
        float v1b = vals[i1b],   v2b = vals[i2b];

        float f_int[FPT], f_xg[FPT], f_djw[FPT];
        eval_elem<G>(x1a, x2a, v1a, v2a, f_int,     f_xg,     f_djw);
        eval_elem<G>(x1b, x2b, v1b, v2b, f_int + G, f_xg + G, f_djw + G);

        static_assert(FPT % 2 == 0, "FPT must be even");
        float2* d0 = reinterpret_cast<float2*>(&s_buf[0][e0 * G]);
        float2* d1 = reinterpret_cast<float2*>(&s_buf[1][e0 * G]);
        float2* d2 = reinterpret_cast<float2*>(&s_buf[2][e0 * G]);
#pragma unroll
        for (int j = 0; j < FPT / 2; ++j) {
            d0[j] = make_float2(f_int[2*j], f_int[2*j+1]);
            d1[j] = make_float2(f_xg[2*j],  f_xg[2*j+1]);
            d2[j] = make_float2(f_djw[2*j], f_djw[2*j+1]);
        }
    } else if (e0 < nElem) {
        for (int k = 0; k < EPT && e0 + k < nElem; ++k) {
            int e = blockStart + e0 + k;
            int2 c = reinterpret_cast<const int2*>(conn)[e];
            int i1 = c.x - 1, i2 = c.y - 1;
            float f_int[G], f_xg[G], f_djw[G];
            eval_elem<G>(coords[i1], coords[i2], vals[i1], vals[i2], f_int, f_xg, f_djw);
#pragma unroll
            for (int g = 0; g < G; ++g) {
                s_buf[0][(e0 + k) * G + g] = f_int[g];
                s_buf[1][(e0 + k) * G + g] = f_xg[g];
                s_buf[2][(e0 + k) * G + g] = f_djw[g];
            }
        }
    }
    __syncthreads();

    const size_t EG   = (size_t)E * G;
    const size_t base = (size_t)blockStart * G;
    const int nFloats = nElem * G;

    if (nElem == ELEM_BLOCK) {
        constexpr int NV = ELEM_BLOCK * G / 4;
#pragma unroll
        for (int sec = 0; sec < 3; ++sec) {
            const float4* src = reinterpret_cast<const float4*>(&s_buf[sec][0]);
            size_t off = (size_t)sec * EG + base;
            if ((off & 3) == 0) {
                float4* dst = reinterpret_cast<float4*>(out + off);
                for (int i = tid; i < NV; i += BLOCK) __stcs(dst + i, src[i]);
            } else {
                for (int i = tid; i < ELEM_BLOCK * G; i += BLOCK)
                    __stcs(out + off + i, s_buf[sec][i]);
            }
        }
    } else {
#pragma unroll
        for (int sec = 0; sec < 3; ++sec) {
            size_t off = (size_t)sec * EG + base;
            for (int i = tid; i < nFloats; i += BLOCK)
                __stcs(out + off + i, s_buf[sec][i]);
        }
    }
}

template <int G>
static void launch(const float* coords, const float* vals, const int* conn,
                   float* out, int E)
{
    constexpr int BLOCK = 256;
    constexpr int EPT   = 2;
    int blocks = (E + BLOCK * EPT - 1) / (BLOCK * EPT);
    meshnn1d_kernel<G, BLOCK, EPT><<<blocks, BLOCK>>>(coords, vals, conn, out, E);
}

extern "C" void kernel_launch(void* const* d_in, const int* in_sizes, int n_in,
                              void* d_out, int out_size)
{
    const float* coords = (const float*)d_in[0];
    const float* vals   = (const float*)d_in[1];
    const int*   conn   = (const int*)d_in[2];
    float*       out    = (float*)d_out;

    int E = in_sizes[2] / 2;
    int G = (E > 0) ? (int)((long long)out_size / (3LL * E)) : 3;
    if (G < 1) G = 1;
    if (G > 5) G = 5;

    switch (G) {
        case 1: launch<1>(coords, vals, conn, out, E); break;
        case 2: launch<2>(coords, vals, conn, out, E); break;
        case 3: launch<3>(coords, vals, conn, out, E); break;
        case 4: launch<4>(coords, vals, conn, out, E); break;
        case 5: launch<5>(coords, vals, conn, out, E); break;
    }
}

// round 12
// speedup vs baseline: 1.3449x; 1.0310x over previous
#include <cuda_runtime.h>
#include <cstdint>

// Gauss-Legendre tables for n = 1..5 (numpy-double -> float32 cast).
__constant__ float XI_TAB[5][5] = {
    { 0.0f, 0.f, 0.f, 0.f, 0.f },
    { -0.5773502691896258f, 0.5773502691896258f, 0.f, 0.f, 0.f },
    { -0.7745966692414834f, 0.0f, 0.7745966692414834f, 0.f, 0.f },
    { -0.8611363115940526f, -0.3399810435848563f, 0.3399810435848563f, 0.8611363115940526f, 0.f },
    { 0.0f, -0.5384693101056831f, 0.5384693101056831f, -0.9061798459386640f, 0.9061798459386640f },
};
__constant__ float W_TAB[5][5] = {
    { 2.0f, 0.f, 0.f, 0.f, 0.f },
    { 1.0f, 1.0f, 0.f, 0.f, 0.f },
    { 0.5555555555555556f, 0.8888888888888889f, 0.5555555555555556f, 0.f, 0.f },
    { 0.3478548451374538f, 0.6521451548625461f, 0.6521451548625461f, 0.3478548451374538f, 0.f },
    { 0.5688888888888889f, 0.4786286704993665f, 0.4786286704993665f, 0.2369268850561891f, 0.2369268850561891f },
};

// Rounding-critical path (must match reference bit-exactly): t and x_g only.
// Given bit-exact x_g, (x_g - x1) is exact (Sterbenz) and 2*(...) exact, so
// num * rcp(dx) and FMA-folded shape functions perturb results ~1e-7 rel.
template <int G>
__device__ __forceinline__ void eval_elem(float x1, float x2, float v1, float v2,
                                          float* f_int, float* f_xg, float* f_djw)
{
    float dx   = __fsub_rn(x2, x1);
    float detJ = __fmul_rn(dx, 0.5f);
    float rcp  = __frcp_rn(dx);
    float d    = __fmul_rn(0.5f, __fsub_rn(v2, v1));
    float s    = __fmul_rn(0.5f, __fadd_rn(v1, v2));
#pragma unroll
    for (int g = 0; g < G; ++g) {
        float xi  = XI_TAB[G - 1][g];
        float w   = W_TAB[G - 1][g];
        float t   = __fmul_rn(__fmul_rn(__fadd_rn(xi, 1.0f), dx), 0.5f);
        float x_g = __fadd_rn(x1, t);
        float num = __fmul_rn(2.0f, __fsub_rn(x_g, x1));   // exact
        float ref = __fmaf_rn(num, rcp, -1.0f);
        f_int[g] = __fmaf_rn(ref, d, s);
        f_xg[g]  = x_g;
        f_djw[g] = __fmul_rn(detJ, w);
    }
}

// Warp-autonomous staging + flush: each warp stages its own 64 elements into
// a private smem slice and flushes it after __syncwarp() — no block barrier,
// warps' gather/compute/store phases overlap freely. 32-bit offset math
// throughout (3*E*G < 2^31). Bank audit: STS.64 @6*lane words: half-warp
// phases cover all 32 banks once; LDS.128 @4*lane: quarter-warp phases clean.
template <int G, int BLOCK, int EPT>
__global__ void __launch_bounds__(BLOCK, 8) meshnn1d_kernel(
    const float* __restrict__ coords,
    const float* __restrict__ vals,
    const int*   __restrict__ conn,    // [E,2] int32, 1-based
    float* __restrict__ out,           // [3, E, G] : interpol | x_g | detJ_w
    int E)
{
    constexpr int ELEM_BLOCK = BLOCK * EPT;
    constexpr int FPT        = EPT * G;            // floats / thread / section
    constexpr int WARP_ELEMS = 32 * EPT;           // 64
    constexpr int WARP_FLOATS = WARP_ELEMS * G;    // 192 floats / warp / section
    constexpr int NWARPS     = BLOCK / 32;
    __shared__ float s_buf[3][NWARPS][WARP_FLOATS];

    const int tid        = threadIdx.x;
    const int lane       = tid & 31;
    const int wrp        = tid >> 5;
    const int blockStart = blockIdx.x * ELEM_BLOCK;
    const int nElem      = min(ELEM_BLOCK, E - blockStart);

    const unsigned EG   = (unsigned)E * G;
    const unsigned base = (unsigned)blockStart * G;

    if (nElem == ELEM_BLOCK) {
        // ---------- full block: warp-autonomous fast path ----------
        const int e0 = tid * EPT;                  // local element base
        int4 c = __ldcs(reinterpret_cast<const int4*>(conn) +
                        (((unsigned)blockStart + (unsigned)e0) >> 1));
        int i1a = c.x - 1, i2a = c.y - 1;
        int i1b = c.z - 1, i2b = c.w - 1;

        float x1a = coords[i1a], x2a = coords[i2a];
        float x1b = coords[i1b], x2b = coords[i2b];
        float v1a = vals[i1a],   v2a = vals[i2a];
        float v1b = vals[i1b],   v2b = vals[i2b];

        float f_int[FPT], f_xg[FPT], f_djw[FPT];
        eval_elem<G>(x1a, x2a, v1a, v2a, f_int,     f_xg,     f_djw);
        eval_elem<G>(x1b, x2b, v1b, v2b, f_int + G, f_xg + G, f_djw + G);

        static_assert(FPT % 2 == 0, "FPT must be even");
        // stage into this warp's slice at word offset FPT*lane
        float2* d0 = reinterpret_cast<float2*>(&s_buf[0][wrp][lane * FPT]);
        float2* d1 = reinterpret_cast<float2*>(&s_buf[1][wrp][lane * FPT]);
        float2* d2 = reinterpret_cast<float2*>(&s_buf[2][wrp][lane * FPT]);
#pragma unroll
        for (int j = 0; j < FPT / 2; ++j) {
            d0[j] = make_float2(f_int[2*j], f_int[2*j+1]);
            d1[j] = make_float2(f_xg[2*j],  f_xg[2*j+1]);
            d2[j] = make_float2(f_djw[2*j], f_djw[2*j+1]);
        }
        __syncwarp();

        // flush own warp slice: WARP_FLOATS/4 float4 per section
        constexpr int NV = WARP_FLOATS / 4;        // 48 for G=3
        const unsigned wbase = base + (unsigned)wrp * WARP_FLOATS;
        if (((EG | wbase) & 3u) == 0u) {
#pragma unroll
            for (int sec = 0; sec < 3; ++sec) {
                const float4* src = reinterpret_cast<const float4*>(&s_buf[sec][wrp][0]);
                float4* dst = reinterpret_cast<float4*>(out + (unsigned)sec * EG + wbase);
#pragma unroll
                for (int r = 0; r < (NV + 31) / 32; ++r) {
                    int i = r * 32 + lane;
                    if (NV % 32 == 0 || i < NV) __stcs(dst + i, src[i]);
                }
            }
        } else {
#pragma unroll
            for (int sec = 0; sec < 3; ++sec) {
                unsigned off = (unsigned)sec * EG + wbase;
                for (int i = lane; i < WARP_FLOATS; i += 32)
                    __stcs(out + off + i, s_buf[sec][wrp][i]);
            }
        }
    } else {
        // ---------- tail block (block-uniform branch): synced scalar path ----------
        const int e0 = tid * EPT;
        if (e0 < nElem) {
            for (int k = 0; k < EPT && e0 + k < nElem; ++k) {
                int e = blockStart + e0 + k;
                int2 c = reinterpret_cast<const int2*>(conn)[e];
                int i1 = c.x - 1, i2 = c.y - 1;
                float f_int[G], f_xg[G], f_djw[G];
                eval_elem<G>(coords[i1], coords[i2], vals[i1], vals[i2],
                             f_int, f_xg, f_djw);
                int lw = (e0 + k) / WARP_ELEMS;        // owning warp slice
                int lo = ((e0 + k) % WARP_ELEMS) * G;
#pragma unroll
                for (int g = 0; g < G; ++g) {
                    s_buf[0][lw][lo + g] = f_int[g];
                    s_buf[1][lw][lo + g] = f_xg[g];
                    s_buf[2][lw][lo + g] = f_djw[g];
                }
            }
        }
        __syncthreads();
        const int nFloats = nElem * G;
#pragma unroll
        for (int sec = 0; sec < 3; ++sec) {
            unsigned off = (unsigned)sec * EG + base;
            for (int i = tid; i < nFloats; i += BLOCK)
                __stcs(out + off + i,
                       s_buf[sec][i / WARP_FLOATS][i % WARP_FLOATS]);
        }
    }
}

template <int G>
static void launch(const float* coords, const float* vals, const int* conn,
                   float* out, int E)
{
    constexpr int BLOCK = 256;
    constexpr int EPT   = 2;
    int blocks = (E + BLOCK * EPT - 1) / (BLOCK * EPT);
    meshnn1d_kernel<G, BLOCK, EPT><<<blocks, BLOCK>>>(coords, vals, conn, out, E);
}

extern "C" void kernel_launch(void* const* d_in, const int* in_sizes, int n_in,
                              void* d_out, int out_size)
{
    const float* coords = (const float*)d_in[0];
    const float* vals   = (const float*)d_in[1];
    const int*   conn   = (const int*)d_in[2];
    float*       out    = (float*)d_out;

    int E = in_sizes[2] / 2;
    int G = (E > 0) ? (int)((long long)out_size / (3LL * E)) : 3;
    if (G < 1) G = 1;
    if (G > 5) G = 5;

    switch (G) {
        case 1: launch<1>(coords, vals, conn, out, E); break;
        case 2: launch<2>(coords, vals, conn, out, E); break;
        case 3: launch<3>(coords, vals, conn, out, E); break;
        case 4: launch<4>(coords, vals, conn, out, E); break;
        case 5: launch<5>(coords, vals, conn, out, E); break;
    }
}